// round 15
// baseline (speedup 1.0000x reference)
#include <cuda_runtime.h>
#include <cuda_bf16.h>
#include <cstdint>

#define HID      128
#define NNODES   50000
#define NEDGES   640000
#define NLAYERS  6

// half-word (bf16) smem layout; stride 136 halves = 272B -> LDSM conflict-free
#define SAH 136
#define SWH 136

// unified layout (all MMA kernels): 64-row A pair + HALF (64-row) W pair
#define A_HIo 0
#define A_LOo (64 * SAH)
#define W_HIo (2 * 64 * SAH)                // 17408
#define W_LOo (W_HIo + 64 * SWH)
#define SMEM_HALVES (W_HIo + 2 * 64 * SWH)  // 34816 halves
#define SMEM_DYN (SMEM_HALVES * 2)          // 69632 B -> 3 CTAs/SM

// split-weight pool: per-layer 896 rows of 128
#define WPOOL_L   (896 * 128)
#define OFF_EW1   0
#define OFF_EW2   (384 * 128)
#define OFF_NW1   (512 * 128)
#define OFF_NW2   (768 * 128)
#define NWSPLIT   (NLAYERS * WPOOL_L)

// ---------------- device scratch --------------------------------------------
__device__ float g_x[(size_t)NNODES * HID];
__device__ float g_sum[(size_t)NNODES * HID];
__device__ float g_ef[(size_t)NEDGES * HID];
__device__ float g_pa[(size_t)NNODES * HID];
__device__ float g_pb[(size_t)NNODES * HID];
__device__ float g_cnt[NNODES];
__device__ float g_cntinv[NNODES];
__device__ int   g_src[NEDGES];
__device__ int   g_dst[NEDGES];
__device__ unsigned int g_idx_is_i32;
__device__ unsigned short g_wh[NWSPLIT];
__device__ unsigned short g_wl[NWSPLIT];

// ---------------- helpers ----------------------------------------------------
__device__ __forceinline__ unsigned short b2u(__nv_bfloat16 b) {
    return *reinterpret_cast<unsigned short*>(&b);
}
__device__ __forceinline__ void bsplit(float v, unsigned short& h, unsigned short& l) {
    __nv_bfloat16 hb = __float2bfloat16(v);
    float hf = __bfloat162float(hb);
    __nv_bfloat16 lb = __float2bfloat16(v - hf);
    h = b2u(hb); l = b2u(lb);
}
__device__ __forceinline__ uint32_t smem_u32(const void* p) {
    uint32_t a;
    asm("{ .reg .u64 t; cvta.to.shared.u64 t, %1; cvt.u32.u64 %0, t; }"
        : "=r"(a) : "l"(p));
    return a;
}

#define MMAB(d, a, b0, b1)                                                     \
    asm volatile("mma.sync.aligned.m16n8k16.row.col.f32.bf16.bf16.f32 "        \
        "{%0,%1,%2,%3},{%4,%5,%6,%7},{%8,%9},{%0,%1,%2,%3};"                   \
        : "+f"((d)[0]), "+f"((d)[1]), "+f"((d)[2]), "+f"((d)[3])               \
        : "r"((a)[0]), "r"((a)[1]), "r"((a)[2]), "r"((a)[3]),                  \
          "r"(b0), "r"(b1))

#define LDSM_X4(r0, r1, r2, r3, addr)                                          \
    asm volatile("ldmatrix.sync.aligned.m8n8.x4.shared.b16 {%0,%1,%2,%3}, [%4];" \
        : "=r"(r0), "=r"(r1), "=r"(r2), "=r"(r3) : "r"(addr))

#define LDSM_X4T(r0, r1, r2, r3, addr)                                         \
    asm volatile("ldmatrix.sync.aligned.m8n8.x4.trans.shared.b16 {%0,%1,%2,%3}, [%4];" \
        : "=r"(r0), "=r"(r1), "=r"(r2), "=r"(r3) : "r"(addr))

#define REDV4(ptr, m)                                                          \
    asm volatile("red.global.add.v4.f32 [%0], {%1,%2,%3,%4};"                  \
        :: "l"(ptr), "f"((m).x), "f"((m).y), "f"((m).z), "f"((m).w) : "memory")

// stage HALF (64 k-rows) of a pre-split 128x128 weight tile
__device__ __forceinline__ void stage_w_half(unsigned short* smh, int layer,
                                             int sect, int khalf, int tid) {
    const unsigned short* wh = g_wh + (size_t)layer * WPOOL_L + sect + khalf * 64 * 128;
    const unsigned short* wl = g_wl + (size_t)layer * WPOOL_L + sect + khalf * 64 * 128;
    #pragma unroll
    for (int i = 0; i < 4; i++) {
        int lin = tid + i * 256;            // 1024 uint4 = 64 rows x 16
        int r = lin >> 4, q = (lin & 15) * 8;
        *(uint4*)(smh + W_HIo + r * SWH + q) = *(const uint4*)(wh + r * 128 + q);
        *(uint4*)(smh + W_LOo + r * SWH + q) = *(const uint4*)(wl + r * 128 + q);
    }
}

// stage one fp32 row quad into A tiles
__device__ __forceinline__ void stage_a4(unsigned short* smh, int r, int q, float4 v) {
    ushort4 h, l;
    bsplit(v.x, h.x, l.x); bsplit(v.y, h.y, l.y);
    bsplit(v.z, h.z, l.z); bsplit(v.w, h.w, l.w);
    *(ushort4*)(smh + A_HIo + r * SAH + q) = h;
    *(ushort4*)(smh + A_LOo + r * SAH + q) = l;
}

// half-K (64) 64x128 GEMM accumulate, warp tile 32x32
// acol = 0 or 64: which half of A's K columns pairs with the staged W half.
__device__ __forceinline__ void gemm_mma_h(float acc[2][4][4], uint32_t smu,
                                           int acol, int m0, int n0, int lane) {
    int lr = lane & 15;
    int lh = (lane >> 4) << 3;
    #pragma unroll 2
    for (int ks = 0; ks < 4; ks++) {
        int k0 = ks * 16;
        uint32_t ah[2][4], al[2][4];
        #pragma unroll
        for (int mt = 0; mt < 2; mt++) {
            uint32_t ad = smu + 2u * (A_HIo + (m0 + mt * 16 + lr) * SAH + acol + k0 + lh);
            LDSM_X4(ah[mt][0], ah[mt][1], ah[mt][2], ah[mt][3], ad);
            LDSM_X4(al[mt][0], al[mt][1], al[mt][2], al[mt][3], ad + 2u * A_LOo);
        }
        #pragma unroll
        for (int np = 0; np < 2; np++) {
            uint32_t wd = smu + 2u * (W_HIo + (k0 + lr) * SWH + n0 + np * 16 + lh);
            uint32_t bh[4], bl[4];
            LDSM_X4T(bh[0], bh[1], bh[2], bh[3], wd);
            LDSM_X4T(bl[0], bl[1], bl[2], bl[3], wd + 2u * (W_LOo - W_HIo));
            #pragma unroll
            for (int sub = 0; sub < 2; sub++) {
                int nt = np * 2 + sub;
                #pragma unroll
                for (int mt = 0; mt < 2; mt++) {
                    MMAB(acc[mt][nt], ah[mt], bh[2 * sub], bh[2 * sub + 1]);
                    MMAB(acc[mt][nt], ah[mt], bl[2 * sub], bl[2 * sub + 1]);
                    MMAB(acc[mt][nt], al[mt], bh[2 * sub], bh[2 * sub + 1]);
                }
            }
        }
    }
}

// full-K GEMM = two half-K passes with a W restage between
__device__ __forceinline__ void gemm_fullk(float acc[2][4][4], unsigned short* smh,
                                           uint32_t smu, int layer, int sect,
                                           int m0, int n0, int lane, int tid) {
    stage_w_half(smh, layer, sect, 0, tid);
    __syncthreads();
    gemm_mma_h(acc, smu, 0, m0, n0, lane);
    __syncthreads();
    stage_w_half(smh, layer, sect, 1, tid);
    __syncthreads();
    gemm_mma_h(acc, smu, 64, m0, n0, lane);
}

#define ACC_ZERO(acc)                                                          \
    _Pragma("unroll") for (int _a = 0; _a < 2; _a++)                           \
    _Pragma("unroll") for (int _b = 0; _b < 4; _b++)                           \
    _Pragma("unroll") for (int _c = 0; _c < 4; _c++) (acc)[_a][_b][_c] = 0.f

// ---------------- prelude kernels -------------------------------------------
__global__ void zero_detect_kernel(const unsigned int* __restrict__ w) {
    size_t i = (size_t)blockIdx.x * blockDim.x + threadIdx.x;
    size_t n4 = (size_t)NNODES * HID / 4;
    if (i == 0) g_idx_is_i32 = 0u;
    if (i < n4) {
        float4 z = make_float4(0.f, 0.f, 0.f, 0.f);
        ((float4*)g_x)[i]   = z;
        ((float4*)g_sum)[i] = z;
        ((float4*)g_pa)[i]  = z;
        ((float4*)g_pb)[i]  = z;
    }
    if (i < NNODES) g_cnt[i] = 0.0f;
    if (i < NEDGES && w[2 * i + 1] != 0u) atomicOr(&g_idx_is_i32, 1u);
}

#define CONV_BLOCKS ((NEDGES + 255) / 256)
__global__ void convert_wsplit_kernel(const void* __restrict__ ei,
                                      const float* __restrict__ ew1,
                                      const float* __restrict__ ew2,
                                      const float* __restrict__ nw1,
                                      const float* __restrict__ nw2) {
    int b = blockIdx.x;
    if (b < CONV_BLOCKS) {
        int e = b * 256 + threadIdx.x;
        if (e >= NEDGES) return;
        if (g_idx_is_i32) {
            const int* p = (const int*)ei;
            g_src[e] = p[e];
            g_dst[e] = p[NEDGES + e];
        } else {
            const long long* p = (const long long*)ei;
            g_src[e] = (int)p[e];
            g_dst[e] = (int)p[NEDGES + e];
        }
        return;
    }
    int i = (b - CONV_BLOCKS) * 256 + threadIdx.x;
    if (i >= NWSPLIT) return;
    int l = i / WPOOL_L, r = i % WPOOL_L;
    float v;
    if (r < OFF_EW2)       v = ew1[(size_t)l * 384 * 128 + r];
    else if (r < OFF_NW1)  v = ew2[(size_t)l * 128 * 128 + (r - OFF_EW2)];
    else if (r < OFF_NW2)  v = nw1[(size_t)l * 256 * 128 + (r - OFF_NW1)];
    else                   v = nw2[(size_t)l * 128 * 128 + (r - OFF_NW2)];
    bsplit(v, g_wh[i], g_wl[i]);
}

__global__ void encode_degree_kernel(const float* __restrict__ ea,
                                     const float* __restrict__ w,
                                     const float* __restrict__ b) {
    int gid = blockIdx.x * 256 + threadIdx.x;
    int e = gid >> 5, q = gid & 31;
    if (e >= NEDGES) return;
    float a0 = __ldg(ea + (size_t)e * 3 + 0);
    float a1 = __ldg(ea + (size_t)e * 3 + 1);
    float a2 = __ldg(ea + (size_t)e * 3 + 2);
    float4 w0 = __ldg((const float4*)w + q);
    float4 w1 = __ldg((const float4*)(w + 128) + q);
    float4 w2 = __ldg((const float4*)(w + 256) + q);
    float4 bb = __ldg((const float4*)b + q);
    float4 r;
    r.x = bb.x + a0 * w0.x + a1 * w1.x + a2 * w2.x;
    r.y = bb.y + a0 * w0.y + a1 * w1.y + a2 * w2.y;
    r.z = bb.z + a0 * w0.z + a1 * w1.z + a2 * w2.z;
    r.w = bb.w + a0 * w0.w + a1 * w1.w + a2 * w2.w;
    ((float4*)g_ef)[(size_t)e * 32 + q] = r;
    if (q == 0) {
        int d = g_dst[e];
        if (d >= 0 && d < NNODES) atomicAdd(&g_cnt[d], 1.0f);
    }
}

__global__ void cntinv_kernel() {
    int n = blockIdx.x * 256 + threadIdx.x;
    if (n < NNODES) g_cntinv[n] = 1.0f / fmaxf(g_cnt[n], 1.0f);
}

// ---------------- proj: Pa = x@W1a, Pb = x@W1b (layers >= 1) -----------------
__global__ void __launch_bounds__(256, 3)
proj_kernel(int layer) {
    extern __shared__ unsigned short smh[];
    uint32_t smu = smem_u32(smh);
    int tid = threadIdx.x, lane = tid & 31, warp = tid >> 5;
    int g = lane >> 2, t = lane & 3;
    int m0 = (warp >> 2) * 32, n0 = (warp & 3) * 32;
    int b0n = blockIdx.x * 64;

    #pragma unroll
    for (int i = 0; i < 8; i++) {
        int lin = tid + i * 256;
        int r = lin >> 5, q = (lin & 31) * 4;
        int n = b0n + r; if (n >= NNODES) n = NNODES - 1;
        stage_a4(smh, r, q, *(const float4*)(g_x + (size_t)n * HID + q));
    }

    float acc[2][4][4];
    ACC_ZERO(acc);
    gemm_fullk(acc, smh, smu, layer, OFF_EW1, m0, n0, lane, tid);

    #pragma unroll
    for (int mt = 0; mt < 2; mt++)
        #pragma unroll
        for (int h = 0; h < 2; h++) {
            int r = m0 + mt * 16 + h * 8 + g;
            int gn = b0n + r;
            if (gn >= NNODES) continue;
            #pragma unroll
            for (int nt = 0; nt < 4; nt++) {
                int c0 = n0 + nt * 8 + 2 * t;
                *(float2*)(g_pa + (size_t)gn * HID + c0) =
                    make_float2(acc[mt][nt][2 * h], acc[mt][nt][2 * h + 1]);
            }
        }
    __syncthreads();

    ACC_ZERO(acc);
    gemm_fullk(acc, smh, smu, layer, OFF_EW1 + 128 * 128, m0, n0, lane, tid);

    #pragma unroll
    for (int mt = 0; mt < 2; mt++)
        #pragma unroll
        for (int h = 0; h < 2; h++) {
            int r = m0 + mt * 16 + h * 8 + g;
            int gn = b0n + r;
            if (gn >= NNODES) continue;
            #pragma unroll
            for (int nt = 0; nt < 4; nt++) {
                int c0 = n0 + nt * 8 + 2 * t;
                *(float2*)(g_pb + (size_t)gn * HID + c0) =
                    make_float2(acc[mt][nt][2 * h], acc[mt][nt][2 * h + 1]);
            }
        }
}

// ---------------- edge: half-K W staging, 3 CTAs/SM --------------------------
// h = relu(ef@W1c + Pa[dst] + Pb[src] + b1);  m = h@W2 + b2
__global__ void __launch_bounds__(256, 3)
edge_kernel(int layer, const float* __restrict__ b1, const float* __restrict__ b2) {
    extern __shared__ unsigned short smh[];
    uint32_t smu = smem_u32(smh);
    __shared__ float s_b1[128], s_b2[128];
    __shared__ int   s_src[64], s_dst[64];

    int tid = threadIdx.x, lane = tid & 31, warp = tid >> 5;
    int g = lane >> 2, t = lane & 3;
    int m0 = (warp >> 2) * 32, n0 = (warp & 3) * 32;
    int e0 = blockIdx.x * 64;

    if (tid < 128) { s_b1[tid] = b1[tid]; s_b2[tid] = b2[tid]; }
    if (tid < 64)  { s_src[tid] = g_src[e0 + tid]; s_dst[tid] = g_dst[e0 + tid]; }

    #pragma unroll
    for (int i = 0; i < 8; i++) {
        int lin = tid + i * 256;
        int r = lin >> 5, q = (lin & 31) * 4;
        stage_a4(smh, r, q, *(const float4*)(g_ef + (size_t)(e0 + r) * HID + q));
    }

    float acc[2][4][4];
    ACC_ZERO(acc);
    gemm_fullk(acc, smh, smu, layer, OFF_EW1 + 256 * 128, m0, n0, lane, tid);
    __syncthreads();

    // h = relu(acc + Pa[dst] + Pb[src] + b1) -> A tiles
    #pragma unroll
    for (int mt = 0; mt < 2; mt++)
        #pragma unroll
        for (int h = 0; h < 2; h++) {
            int r = m0 + mt * 16 + h * 8 + g;
            int sd = s_dst[r], ss = s_src[r];
            #pragma unroll
            for (int nt = 0; nt < 4; nt++) {
                int c0 = n0 + nt * 8 + 2 * t;
                float2 pa = *(const float2*)(g_pa + (size_t)sd * HID + c0);
                float2 pb = *(const float2*)(g_pb + (size_t)ss * HID + c0);
                float v0 = fmaxf(acc[mt][nt][2 * h]     + pa.x + pb.x + s_b1[c0],     0.f);
                float v1 = fmaxf(acc[mt][nt][2 * h + 1] + pa.y + pb.y + s_b1[c0 + 1], 0.f);
                ushort2 hh, ll;
                bsplit(v0, hh.x, ll.x); bsplit(v1, hh.y, ll.y);
                *(ushort2*)(smh + A_HIo + r * SAH + c0) = hh;
                *(ushort2*)(smh + A_LOo + r * SAH + c0) = ll;
            }
        }

    ACC_ZERO(acc);
    gemm_fullk(acc, smh, smu, layer, OFF_EW2, m0, n0, lane, tid);
    __syncthreads();        // A tiles dead; reuse as fp32 m-buffer

    float* smf = (float*)smh;
    #pragma unroll
    for (int mt = 0; mt < 2; mt++)
        #pragma unroll
        for (int h = 0; h < 2; h++) {
            int r = m0 + mt * 16 + h * 8 + g;
            #pragma unroll
            for (int nt = 0; nt < 4; nt++) {
                int c0 = n0 + nt * 8 + 2 * t;
                smf[r * 132 + c0]     = acc[mt][nt][2 * h]     + s_b2[c0];
                smf[r * 132 + c0 + 1] = acc[mt][nt][2 * h + 1] + s_b2[c0 + 1];
            }
        }
    __syncthreads();

    // coalesced: ef += m (float4), g_sum[dst] += m (red.v4)
    #pragma unroll
    for (int i = 0; i < 8; i++) {
        int lin = tid + i * 256;
        int row = lin >> 5, q = (lin & 31) * 4;
        float4 m = *(const float4*)(smf + row * 132 + q);
        float4* efp = (float4*)(g_ef + (size_t)(e0 + row) * HID + q);
        float4 eo = *efp;
        eo.x += m.x; eo.y += m.y; eo.z += m.z; eo.w += m.w;
        *efp = eo;
        float* sp = g_sum + (size_t)s_dst[row] * HID + q;
        REDV4(sp, m);
    }
}

// ---------------- node: x += MLP([x | mean_aggr]) ---------------------------
__global__ void __launch_bounds__(256, 3)
node_kernel(int layer, const float* __restrict__ b1, const float* __restrict__ b2) {
    extern __shared__ unsigned short smh[];
    uint32_t smu = smem_u32(smh);
    __shared__ float s_b1[128], s_b2[128], s_scale[64];

    int tid = threadIdx.x, lane = tid & 31, warp = tid >> 5;
    int g = lane >> 2, t = lane & 3;
    int m0 = (warp >> 2) * 32, n0 = (warp & 3) * 32;
    int b0n = blockIdx.x * 64;

    if (tid < 128) { s_b1[tid] = b1[tid]; s_b2[tid] = b2[tid]; }
    if (tid < 64) {
        int n = b0n + tid;
        s_scale[tid] = (n < NNODES) ? g_cntinv[n] : 0.0f;
    }

    float acc[2][4][4];
    ACC_ZERO(acc);

    // chunk 0: A = x
    #pragma unroll
    for (int i = 0; i < 8; i++) {
        int lin = tid + i * 256;
        int r = lin >> 5, q = (lin & 31) * 4;
        int n = b0n + r; if (n >= NNODES) n = NNODES - 1;
        stage_a4(smh, r, q, *(const float4*)(g_x + (size_t)n * HID + q));
    }
    gemm_fullk(acc, smh, smu, layer, OFF_NW1, m0, n0, lane, tid);
    __syncthreads();

    // chunk 1: A = mean_aggr (consume & clear)
    #pragma unroll
    for (int i = 0; i < 8; i++) {
        int lin = tid + i * 256;
        int r = lin >> 5, q = (lin & 31) * 4;
        int n = b0n + r;
        bool valid = (n < NNODES);
        if (!valid) n = NNODES - 1;
        float4* sp = (float4*)(g_sum + (size_t)n * HID + q);
        float4 v = *sp;
        if (valid) *sp = make_float4(0.f, 0.f, 0.f, 0.f);
        float s = s_scale[r];
        v.x *= s; v.y *= s; v.z *= s; v.w *= s;
        stage_a4(smh, r, q, v);
    }
    gemm_fullk(acc, smh, smu, layer, OFF_NW1 + 128 * 128, m0, n0, lane, tid);
    __syncthreads();

    // h = relu(acc + b1) -> A tiles
    #pragma unroll
    for (int mt = 0; mt < 2; mt++)
        #pragma unroll
        for (int h = 0; h < 2; h++) {
            int r = m0 + mt * 16 + h * 8 + g;
            #pragma unroll
            for (int nt = 0; nt < 4; nt++) {
                int c0 = n0 + nt * 8 + 2 * t;
                float v0 = fmaxf(acc[mt][nt][2 * h]     + s_b1[c0],     0.f);
                float v1 = fmaxf(acc[mt][nt][2 * h + 1] + s_b1[c0 + 1], 0.f);
                ushort2 hh, ll;
                bsplit(v0, hh.x, ll.x); bsplit(v1, hh.y, ll.y);
                *(ushort2*)(smh + A_HIo + r * SAH + c0) = hh;
                *(ushort2*)(smh + A_LOo + r * SAH + c0) = ll;
            }
        }

    ACC_ZERO(acc);
    gemm_fullk(acc, smh, smu, layer, OFF_NW2, m0, n0, lane, tid);

    #pragma unroll
    for (int mt = 0; mt < 2; mt++)
        #pragma unroll
        for (int h = 0; h < 2; h++) {
            int r = m0 + mt * 16 + h * 8 + g;
            int gn = b0n + r;
            if (gn >= NNODES) continue;
            #pragma unroll
            for (int nt = 0; nt < 4; nt++) {
                int c0 = n0 + nt * 8 + 2 * t;
                float2* xp = (float2*)(g_x + (size_t)gn * HID + c0);
                float2 xo = *xp;
                xo.x += acc[mt][nt][2 * h]     + s_b2[c0];
                xo.y += acc[mt][nt][2 * h + 1] + s_b2[c0 + 1];
                *xp = xo;
            }
        }
}

// ---------------- decoder + row-normalize -----------------------------------
__global__ void decode_kernel(const float* __restrict__ dw,
                              const float* __restrict__ db,
                              float* __restrict__ out) {
    int w = (blockIdx.x * blockDim.x + threadIdx.x) >> 5;
    int lane = threadIdx.x & 31;
    if (w >= NNODES) return;
    const float* xr = g_x + (size_t)w * HID;
    float a0 = 0.f, a1 = 0.f, a2 = 0.f;
    #pragma unroll
    for (int i = 0; i < 4; i++) {
        int k = lane + i * 32;
        float xv = xr[k];
        a0 += xv * __ldg(dw + k * 3 + 0);
        a1 += xv * __ldg(dw + k * 3 + 1);
        a2 += xv * __ldg(dw + k * 3 + 2);
    }
    #pragma unroll
    for (int o = 16; o; o >>= 1) {
        a0 += __shfl_xor_sync(0xffffffffu, a0, o);
        a1 += __shfl_xor_sync(0xffffffffu, a1, o);
        a2 += __shfl_xor_sync(0xffffffffu, a2, o);
    }
    if (lane == 0) {
        a0 += __ldg(db + 0); a1 += __ldg(db + 1); a2 += __ldg(db + 2);
        float nrm = sqrtf(a0 * a0 + a1 * a1 + a2 * a2);
        float inv = 1.0f / fmaxf(nrm, 1e-12f);
        out[(size_t)w * 3 + 0] = a0 * inv;
        out[(size_t)w * 3 + 1] = a1 * inv;
        out[(size_t)w * 3 + 2] = a2 * inv;
    }
}

// ---------------- launcher ----------------------------------------------------
extern "C" void kernel_launch(void* const* d_in, const int* in_sizes, int n_in,
                              void* d_out, int out_size) {
    (void)in_sizes; (void)n_in; (void)out_size;
    const float* edge_attr = (const float*)d_in[1];
    const void*  ei        = d_in[2];
    const float* enc_w = (const float*)d_in[3];
    const float* enc_b = (const float*)d_in[4];
    const float* dec_w = (const float*)d_in[5];
    const float* dec_b = (const float*)d_in[6];
    const float* ew1   = (const float*)d_in[7];
    const float* eb1   = (const float*)d_in[8];
    const float* ew2   = (const float*)d_in[9];
    const float* eb2   = (const float*)d_in[10];
    const float* nw1   = (const float*)d_in[11];
    const float* nb1   = (const float*)d_in[12];
    const float* nw2   = (const float*)d_in[13];
    const float* nb2   = (const float*)d_in[14];

    cudaFuncSetAttribute(proj_kernel, cudaFuncAttributeMaxDynamicSharedMemorySize, SMEM_DYN);
    cudaFuncSetAttribute(edge_kernel, cudaFuncAttributeMaxDynamicSharedMemorySize, SMEM_DYN);
    cudaFuncSetAttribute(node_kernel, cudaFuncAttributeMaxDynamicSharedMemorySize, SMEM_DYN);
    cudaGetLastError();

    {
        size_t n4 = (size_t)NNODES * HID / 4;
        zero_detect_kernel<<<(unsigned)((n4 + 255) / 256), 256>>>(
            (const unsigned int*)ei);
    }
    {
        int blocks = CONV_BLOCKS + (NWSPLIT + 255) / 256;
        convert_wsplit_kernel<<<blocks, 256>>>(ei, ew1, ew2, nw1, nw2);
    }
    encode_degree_kernel<<<NEDGES * 32 / 256, 256>>>(edge_attr, enc_w, enc_b);

    // #4 edge layer 0 (Pa=Pb=0 from zeroing) -- profiled launch
    edge_kernel<<<NEDGES / 64, 256, SMEM_DYN>>>(0, eb1, eb2);

    cntinv_kernel<<<(NNODES + 255) / 256, 256>>>();
    node_kernel<<<(NNODES + 63) / 64, 256, SMEM_DYN>>>(0, nb1, nb2);

    for (int l = 1; l < NLAYERS; l++) {
        proj_kernel<<<(NNODES + 63) / 64, 256, SMEM_DYN>>>(l);
        edge_kernel<<<NEDGES / 64, 256, SMEM_DYN>>>(
            l, eb1 + (size_t)l * HID, eb2 + (size_t)l * HID);
        node_kernel<<<(NNODES + 63) / 64, 256, SMEM_DYN>>>(
            l, nb1 + (size_t)l * HID, nb2 + (size_t)l * HID);
    }

    decode_kernel<<<(NNODES * 32 + 255) / 256, 256>>>(dec_w, dec_b, (float*)d_out);
}

// round 16
// speedup vs baseline: 1.0775x; 1.0775x over previous
#include <cuda_runtime.h>
#include <cuda_bf16.h>
#include <cstdint>

#define HID      128
#define NNODES   50000
#define NEDGES   640000
#define NLAYERS  6

// half-word (bf16) smem layout; stride 136 halves = 272B -> LDSM conflict-free
#define SAH 136
#define SWH 136

// proj/node layout: 64-row A + full 128-row W pair (2 CTAs/SM)
#define A_HIo 0
#define A_LOo (64 * SAH)
#define W_HIo (2 * 64 * SAH)
#define W_LOo (W_HIo + 128 * SWH)
#define SMEM_HALVES (W_LOo + 128 * SWH)
#define SMEM_DYN (SMEM_HALVES * 2)          // 104448 B -> 2 CTAs/SM

// edge layout: 64-row A + HALF (64-row) W pair (3 CTAs/SM)
#define EA_HI 0
#define EA_LO (64 * SAH)
#define EW_H  (2 * 64 * SAH)                // 17408
#define EW_L  (EW_H + 64 * SWH)
#define SMEM_HALVES_E (EW_H + 2 * 64 * SWH) // 34816 halves
#define SMEM_DYN_E (SMEM_HALVES_E * 2)      // 69632 B -> 3 CTAs/SM

// split-weight pool: per-layer 896 rows of 128
#define WPOOL_L   (896 * 128)
#define OFF_EW1   0
#define OFF_EW2   (384 * 128)
#define OFF_NW1   (512 * 128)
#define OFF_NW2   (768 * 128)
#define NWSPLIT   (NLAYERS * WPOOL_L)

// ---------------- device scratch --------------------------------------------
__device__ float g_x[(size_t)NNODES * HID];
__device__ float g_sum[(size_t)NNODES * HID];
__device__ float g_ef[(size_t)NEDGES * HID];
__device__ float g_pa[(size_t)NNODES * HID];
__device__ float g_pb[(size_t)NNODES * HID];
__device__ float g_cnt[NNODES];
__device__ float g_cntinv[NNODES];
__device__ int   g_src[NEDGES];
__device__ int   g_dst[NEDGES];
__device__ unsigned int g_idx_is_i32;
__device__ unsigned short g_wh[NWSPLIT];
__device__ unsigned short g_wl[NWSPLIT];

// ---------------- helpers ----------------------------------------------------
__device__ __forceinline__ unsigned short b2u(__nv_bfloat16 b) {
    return *reinterpret_cast<unsigned short*>(&b);
}
__device__ __forceinline__ void bsplit(float v, unsigned short& h, unsigned short& l) {
    __nv_bfloat16 hb = __float2bfloat16(v);
    float hf = __bfloat162float(hb);
    __nv_bfloat16 lb = __float2bfloat16(v - hf);
    h = b2u(hb); l = b2u(lb);
}
__device__ __forceinline__ uint32_t smem_u32(const void* p) {
    uint32_t a;
    asm("{ .reg .u64 t; cvta.to.shared.u64 t, %1; cvt.u32.u64 %0, t; }"
        : "=r"(a) : "l"(p));
    return a;
}

#define MMAB(d, a, b0, b1)                                                     \
    asm volatile("mma.sync.aligned.m16n8k16.row.col.f32.bf16.bf16.f32 "        \
        "{%0,%1,%2,%3},{%4,%5,%6,%7},{%8,%9},{%0,%1,%2,%3};"                   \
        : "+f"((d)[0]), "+f"((d)[1]), "+f"((d)[2]), "+f"((d)[3])               \
        : "r"((a)[0]), "r"((a)[1]), "r"((a)[2]), "r"((a)[3]),                  \
          "r"(b0), "r"(b1))

#define LDSM_X4(r0, r1, r2, r3, addr)                                          \
    asm volatile("ldmatrix.sync.aligned.m8n8.x4.shared.b16 {%0,%1,%2,%3}, [%4];" \
        : "=r"(r0), "=r"(r1), "=r"(r2), "=r"(r3) : "r"(addr))

#define LDSM_X4T(r0, r1, r2, r3, addr)                                         \
    asm volatile("ldmatrix.sync.aligned.m8n8.x4.trans.shared.b16 {%0,%1,%2,%3}, [%4];" \
        : "=r"(r0), "=r"(r1), "=r"(r2), "=r"(r3) : "r"(addr))

#define REDV4(ptr, m)                                                          \
    asm volatile("red.global.add.v4.f32 [%0], {%1,%2,%3,%4};"                  \
        :: "l"(ptr), "f"((m).x), "f"((m).y), "f"((m).z), "f"((m).w) : "memory")

#define CP16(dst_u32, src_ptr)                                                 \
    asm volatile("cp.async.ca.shared.global [%0], [%1], 16;"                   \
        :: "r"(dst_u32), "l"(src_ptr) : "memory")
#define CP_COMMIT() asm volatile("cp.async.commit_group;" ::: "memory")
#define CP_WAIT0()  asm volatile("cp.async.wait_group 0;" ::: "memory")

// stage full 128-row pre-split weight pair via cp.async (proj/node)
__device__ __forceinline__ void stage_w(uint32_t smu, int layer, int sect, int tid) {
    const unsigned short* wh = g_wh + (size_t)layer * WPOOL_L + sect;
    const unsigned short* wl = g_wl + (size_t)layer * WPOOL_L + sect;
    #pragma unroll
    for (int i = 0; i < 8; i++) {
        int lin = tid + i * 256;            // 2048 = 128 rows x 16
        int r = lin >> 4, q = (lin & 15) * 8;
        CP16(smu + 2u * (W_HIo + r * SWH + q), wh + r * 128 + q);
        CP16(smu + 2u * (W_LOo + r * SWH + q), wl + r * 128 + q);
    }
    CP_COMMIT();
}

// stage HALF (64 k-rows) weight pair via cp.async (edge)
__device__ __forceinline__ void stage_w_half(uint32_t smu, int layer,
                                             int sect, int khalf, int tid) {
    const unsigned short* wh = g_wh + (size_t)layer * WPOOL_L + sect + khalf * 64 * 128;
    const unsigned short* wl = g_wl + (size_t)layer * WPOOL_L + sect + khalf * 64 * 128;
    #pragma unroll
    for (int i = 0; i < 4; i++) {
        int lin = tid + i * 256;            // 1024 = 64 rows x 16
        int r = lin >> 4, q = (lin & 15) * 8;
        CP16(smu + 2u * (EW_H + r * SWH + q), wh + r * 128 + q);
        CP16(smu + 2u * (EW_L + r * SWH + q), wl + r * 128 + q);
    }
    CP_COMMIT();
}

// stage one fp32 row quad into A tiles
__device__ __forceinline__ void stage_a4(unsigned short* smh, int r, int q, float4 v) {
    ushort4 h, l;
    bsplit(v.x, h.x, l.x); bsplit(v.y, h.y, l.y);
    bsplit(v.z, h.z, l.z); bsplit(v.w, h.w, l.w);
    *(ushort4*)(smh + A_HIo + r * SAH + q) = h;
    *(ushort4*)(smh + A_LOo + r * SAH + q) = l;
}

// full-K (128) 64x128 GEMM, warp tile 32x32 (proj/node; W at W_HIo/W_LOo)
__device__ __forceinline__ void gemm_mma(float acc[2][4][4], uint32_t smu,
                                         int m0, int n0, int lane) {
    int lr = lane & 15;
    int lh = (lane >> 4) << 3;
    #pragma unroll 2
    for (int ks = 0; ks < 8; ks++) {
        int k0 = ks * 16;
        uint32_t ah[2][4], al[2][4];
        #pragma unroll
        for (int mt = 0; mt < 2; mt++) {
            uint32_t ad = smu + 2u * (A_HIo + (m0 + mt * 16 + lr) * SAH + k0 + lh);
            LDSM_X4(ah[mt][0], ah[mt][1], ah[mt][2], ah[mt][3], ad);
            LDSM_X4(al[mt][0], al[mt][1], al[mt][2], al[mt][3], ad + 2u * A_LOo);
        }
        #pragma unroll
        for (int np = 0; np < 2; np++) {
            uint32_t wd = smu + 2u * (W_HIo + (k0 + lr) * SWH + n0 + np * 16 + lh);
            uint32_t bh[4], bl[4];
            LDSM_X4T(bh[0], bh[1], bh[2], bh[3], wd);
            LDSM_X4T(bl[0], bl[1], bl[2], bl[3], wd + 2u * (W_LOo - W_HIo));
            #pragma unroll
            for (int sub = 0; sub < 2; sub++) {
                int nt = np * 2 + sub;
                #pragma unroll
                for (int mt = 0; mt < 2; mt++) {
                    MMAB(acc[mt][nt], ah[mt], bh[2 * sub], bh[2 * sub + 1]);
                    MMAB(acc[mt][nt], ah[mt], bl[2 * sub], bl[2 * sub + 1]);
                    MMAB(acc[mt][nt], al[mt], bh[2 * sub], bh[2 * sub + 1]);
                }
            }
        }
    }
}

// half-K (64) 64x128 GEMM accumulate, warp tile 32x32 (edge; W at EW_H/EW_L)
__device__ __forceinline__ void gemm_mma_h(float acc[2][4][4], uint32_t smu,
                                           int acol, int m0, int n0, int lane) {
    int lr = lane & 15;
    int lh = (lane >> 4) << 3;
    #pragma unroll 2
    for (int ks = 0; ks < 4; ks++) {
        int k0 = ks * 16;
        uint32_t ah[2][4], al[2][4];
        #pragma unroll
        for (int mt = 0; mt < 2; mt++) {
            uint32_t ad = smu + 2u * (EA_HI + (m0 + mt * 16 + lr) * SAH + acol + k0 + lh);
            LDSM_X4(ah[mt][0], ah[mt][1], ah[mt][2], ah[mt][3], ad);
            LDSM_X4(al[mt][0], al[mt][1], al[mt][2], al[mt][3], ad + 2u * EA_LO);
        }
        #pragma unroll
        for (int np = 0; np < 2; np++) {
            uint32_t wd = smu + 2u * (EW_H + (k0 + lr) * SWH + n0 + np * 16 + lh);
            uint32_t bh[4], bl[4];
            LDSM_X4T(bh[0], bh[1], bh[2], bh[3], wd);
            LDSM_X4T(bl[0], bl[1], bl[2], bl[3], wd + 2u * (EW_L - EW_H));
            #pragma unroll
            for (int sub = 0; sub < 2; sub++) {
                int nt = np * 2 + sub;
                #pragma unroll
                for (int mt = 0; mt < 2; mt++) {
                    MMAB(acc[mt][nt], ah[mt], bh[2 * sub], bh[2 * sub + 1]);
                    MMAB(acc[mt][nt], ah[mt], bl[2 * sub], bl[2 * sub + 1]);
                    MMAB(acc[mt][nt], al[mt], bh[2 * sub], bh[2 * sub + 1]);
                }
            }
        }
    }
}

#define ACC_ZERO(acc)                                                          \
    _Pragma("unroll") for (int _a = 0; _a < 2; _a++)                           \
    _Pragma("unroll") for (int _b = 0; _b < 4; _b++)                           \
    _Pragma("unroll") for (int _c = 0; _c < 4; _c++) (acc)[_a][_b][_c] = 0.f

// ---------------- prelude kernels -------------------------------------------
__global__ void zero_detect_kernel(const unsigned int* __restrict__ w) {
    size_t i = (size_t)blockIdx.x * blockDim.x + threadIdx.x;
    size_t n4 = (size_t)NNODES * HID / 4;
    if (i == 0) g_idx_is_i32 = 0u;
    if (i < n4) {
        float4 z = make_float4(0.f, 0.f, 0.f, 0.f);
        ((float4*)g_x)[i]   = z;
        ((float4*)g_sum)[i] = z;
        ((float4*)g_pa)[i]  = z;
        ((float4*)g_pb)[i]  = z;
    }
    if (i < NNODES) g_cnt[i] = 0.0f;
    if (i < NEDGES && w[2 * i + 1] != 0u) atomicOr(&g_idx_is_i32, 1u);
}

#define CONV_BLOCKS ((NEDGES + 255) / 256)
__global__ void convert_wsplit_kernel(const void* __restrict__ ei,
                                      const float* __restrict__ ew1,
                                      const float* __restrict__ ew2,
                                      const float* __restrict__ nw1,
                                      const float* __restrict__ nw2) {
    int b = blockIdx.x;
    if (b < CONV_BLOCKS) {
        int e = b * 256 + threadIdx.x;
        if (e >= NEDGES) return;
        if (g_idx_is_i32) {
            const int* p = (const int*)ei;
            g_src[e] = p[e];
            g_dst[e] = p[NEDGES + e];
        } else {
            const long long* p = (const long long*)ei;
            g_src[e] = (int)p[e];
            g_dst[e] = (int)p[NEDGES + e];
        }
        return;
    }
    int i = (b - CONV_BLOCKS) * 256 + threadIdx.x;
    if (i >= NWSPLIT) return;
    int l = i / WPOOL_L, r = i % WPOOL_L;
    float v;
    if (r < OFF_EW2)       v = ew1[(size_t)l * 384 * 128 + r];
    else if (r < OFF_NW1)  v = ew2[(size_t)l * 128 * 128 + (r - OFF_EW2)];
    else if (r < OFF_NW2)  v = nw1[(size_t)l * 256 * 128 + (r - OFF_NW1)];
    else                   v = nw2[(size_t)l * 128 * 128 + (r - OFF_NW2)];
    bsplit(v, g_wh[i], g_wl[i]);
}

__global__ void encode_degree_kernel(const float* __restrict__ ea,
                                     const float* __restrict__ w,
                                     const float* __restrict__ b) {
    int gid = blockIdx.x * 256 + threadIdx.x;
    int e = gid >> 5, q = gid & 31;
    if (e >= NEDGES) return;
    float a0 = __ldg(ea + (size_t)e * 3 + 0);
    float a1 = __ldg(ea + (size_t)e * 3 + 1);
    float a2 = __ldg(ea + (size_t)e * 3 + 2);
    float4 w0 = __ldg((const float4*)w + q);
    float4 w1 = __ldg((const float4*)(w + 128) + q);
    float4 w2 = __ldg((const float4*)(w + 256) + q);
    float4 bb = __ldg((const float4*)b + q);
    float4 r;
    r.x = bb.x + a0 * w0.x + a1 * w1.x + a2 * w2.x;
    r.y = bb.y + a0 * w0.y + a1 * w1.y + a2 * w2.y;
    r.z = bb.z + a0 * w0.z + a1 * w1.z + a2 * w2.z;
    r.w = bb.w + a0 * w0.w + a1 * w1.w + a2 * w2.w;
    ((float4*)g_ef)[(size_t)e * 32 + q] = r;
    if (q == 0) {
        int d = g_dst[e];
        if (d >= 0 && d < NNODES) atomicAdd(&g_cnt[d], 1.0f);
    }
}

__global__ void cntinv_kernel() {
    int n = blockIdx.x * 256 + threadIdx.x;
    if (n < NNODES) g_cntinv[n] = 1.0f / fmaxf(g_cnt[n], 1.0f);
}

// ---------------- proj: Pa = x@W1a, Pb = x@W1b (layers >= 1) -----------------
__global__ void __launch_bounds__(256, 2)
proj_kernel(int layer) {
    extern __shared__ unsigned short smh[];
    uint32_t smu = smem_u32(smh);
    int tid = threadIdx.x, lane = tid & 31, warp = tid >> 5;
    int g = lane >> 2, t = lane & 3;
    int m0 = (warp >> 2) * 32, n0 = (warp & 3) * 32;
    int b0n = blockIdx.x * 64;

    stage_w(smu, layer, OFF_EW1, tid);
    #pragma unroll
    for (int i = 0; i < 8; i++) {
        int lin = tid + i * 256;
        int r = lin >> 5, q = (lin & 31) * 4;
        int n = b0n + r; if (n >= NNODES) n = NNODES - 1;
        stage_a4(smh, r, q, *(const float4*)(g_x + (size_t)n * HID + q));
    }
    CP_WAIT0();
    __syncthreads();

    float acc[2][4][4];
    ACC_ZERO(acc);
    gemm_mma(acc, smu, m0, n0, lane);

    #pragma unroll
    for (int mt = 0; mt < 2; mt++)
        #pragma unroll
        for (int h = 0; h < 2; h++) {
            int r = m0 + mt * 16 + h * 8 + g;
            int gn = b0n + r;
            if (gn >= NNODES) continue;
            #pragma unroll
            for (int nt = 0; nt < 4; nt++) {
                int c0 = n0 + nt * 8 + 2 * t;
                *(float2*)(g_pa + (size_t)gn * HID + c0) =
                    make_float2(acc[mt][nt][2 * h], acc[mt][nt][2 * h + 1]);
            }
        }
    __syncthreads();
    stage_w(smu, layer, OFF_EW1 + 128 * 128, tid);
    CP_WAIT0();
    __syncthreads();

    ACC_ZERO(acc);
    gemm_mma(acc, smu, m0, n0, lane);

    #pragma unroll
    for (int mt = 0; mt < 2; mt++)
        #pragma unroll
        for (int h = 0; h < 2; h++) {
            int r = m0 + mt * 16 + h * 8 + g;
            int gn = b0n + r;
            if (gn >= NNODES) continue;
            #pragma unroll
            for (int nt = 0; nt < 4; nt++) {
                int c0 = n0 + nt * 8 + 2 * t;
                *(float2*)(g_pb + (size_t)gn * HID + c0) =
                    make_float2(acc[mt][nt][2 * h], acc[mt][nt][2 * h + 1]);
            }
        }
}

// ---------------- edge: half-K W staging (cp.async), 3 CTAs/SM ---------------
// h = relu(ef@W1c + Pa[dst] + Pb[src] + b1);  m = h@W2 + b2
__global__ void __launch_bounds__(256, 3)
edge_kernel(int layer, const float* __restrict__ b1, const float* __restrict__ b2) {
    extern __shared__ unsigned short smh[];
    uint32_t smu = smem_u32(smh);
    __shared__ float s_b1[128], s_b2[128];
    __shared__ int   s_src[64], s_dst[64];

    int tid = threadIdx.x, lane = tid & 31, warp = tid >> 5;
    int g = lane >> 2, t = lane & 3;
    int m0 = (warp >> 2) * 32, n0 = (warp & 3) * 32;
    int e0 = blockIdx.x * 64;

    if (tid < 128) { s_b1[tid] = b1[tid]; s_b2[tid] = b2[tid]; }
    if (tid < 64)  { s_src[tid] = g_src[e0 + tid]; s_dst[tid] = g_dst[e0 + tid]; }

    stage_w_half(smu, layer, OFF_EW1 + 256 * 128, 0, tid);
    #pragma unroll
    for (int i = 0; i < 8; i++) {
        int lin = tid + i * 256;
        int r = lin >> 5, q = (lin & 31) * 4;
        stage_a4(smh, r, q, *(const float4*)(g_ef + (size_t)(e0 + r) * HID + q));
    }
    CP_WAIT0();
    __syncthreads();

    float acc[2][4][4];
    ACC_ZERO(acc);
    gemm_mma_h(acc, smu, 0, m0, n0, lane);
    __syncthreads();
    stage_w_half(smu, layer, OFF_EW1 + 256 * 128, 1, tid);
    CP_WAIT0();
    __syncthreads();
    gemm_mma_h(acc, smu, 64, m0, n0, lane);
    __syncthreads();

    // h = relu(acc + Pa[dst] + Pb[src] + b1) -> A tiles; prefetch W2 half0
    stage_w_half(smu, layer, OFF_EW2, 0, tid);
    #pragma unroll
    for (int mt = 0; mt < 2; mt++)
        #pragma unroll
        for (int h = 0; h < 2; h++) {
            int r = m0 + mt * 16 + h * 8 + g;
            int sd = s_dst[r], ss = s_src[r];
            #pragma unroll
            for (int nt = 0; nt < 4; nt++) {
                int c0 = n0 + nt * 8 + 2 * t;
                float2 pa = *(const float2*)(g_pa + (size_t)sd * HID + c0);
                float2 pb = *(const float2*)(g_pb + (size_t)ss * HID + c0);
                float v0 = fmaxf(acc[mt][nt][2 * h]     + pa.x + pb.x + s_b1[c0],     0.f);
                float v1 = fmaxf(acc[mt][nt][2 * h + 1] + pa.y + pb.y + s_b1[c0 + 1], 0.f);
                ushort2 hh, ll;
                bsplit(v0, hh.x, ll.x); bsplit(v1, hh.y, ll.y);
                *(ushort2*)(smh + EA_HI + r * SAH + c0) = hh;
                *(ushort2*)(smh + EA_LO + r * SAH + c0) = ll;
            }
        }
    CP_WAIT0();
    __syncthreads();

    ACC_ZERO(acc);
    gemm_mma_h(acc, smu, 0, m0, n0, lane);
    __syncthreads();
    stage_w_half(smu, layer, OFF_EW2, 1, tid);
    CP_WAIT0();
    __syncthreads();
    gemm_mma_h(acc, smu, 64, m0, n0, lane);
    __syncthreads();        // A tiles dead; reuse as fp32 m-buffer

    float* smf = (float*)smh;
    #pragma unroll
    for (int mt = 0; mt < 2; mt++)
        #pragma unroll
        for (int h = 0; h < 2; h++) {
            int r = m0 + mt * 16 + h * 8 + g;
            #pragma unroll
            for (int nt = 0; nt < 4; nt++) {
                int c0 = n0 + nt * 8 + 2 * t;
                smf[r * 132 + c0]     = acc[mt][nt][2 * h]     + s_b2[c0];
                smf[r * 132 + c0 + 1] = acc[mt][nt][2 * h + 1] + s_b2[c0 + 1];
            }
        }
    __syncthreads();

    // coalesced: ef += m (float4), g_sum[dst] += m (red.v4)
    #pragma unroll
    for (int i = 0; i < 8; i++) {
        int lin = tid + i * 256;
        int row = lin >> 5, q = (lin & 31) * 4;
        float4 m = *(const float4*)(smf + row * 132 + q);
        float4* efp = (float4*)(g_ef + (size_t)(e0 + row) * HID + q);
        float4 eo = *efp;
        eo.x += m.x; eo.y += m.y; eo.z += m.z; eo.w += m.w;
        *efp = eo;
        float* sp = g_sum + (size_t)s_dst[row] * HID + q;
        REDV4(sp, m);
    }
}

// ---------------- node: x += MLP([x | mean_aggr]) ---------------------------
__global__ void __launch_bounds__(256, 2)
node_kernel(int layer, const float* __restrict__ b1, const float* __restrict__ b2) {
    extern __shared__ unsigned short smh[];
    uint32_t smu = smem_u32(smh);
    __shared__ float s_b1[128], s_b2[128], s_scale[64];

    int tid = threadIdx.x, lane = tid & 31, warp = tid >> 5;
    int g = lane >> 2, t = lane & 3;
    int m0 = (warp >> 2) * 32, n0 = (warp & 3) * 32;
    int b0n = blockIdx.x * 64;

    if (tid < 128) { s_b1[tid] = b1[tid]; s_b2[tid] = b2[tid]; }
    if (tid < 64) {
        int n = b0n + tid;
        s_scale[tid] = (n < NNODES) ? g_cntinv[n] : 0.0f;
    }

    float acc[2][4][4];
    ACC_ZERO(acc);

    stage_w(smu, layer, OFF_NW1, tid);
    #pragma unroll
    for (int i = 0; i < 8; i++) {
        int lin = tid + i * 256;
        int r = lin >> 5, q = (lin & 31) * 4;
        int n = b0n + r; if (n >= NNODES) n = NNODES - 1;
        stage_a4(smh, r, q, *(const float4*)(g_x + (size_t)n * HID + q));
    }
    CP_WAIT0();
    __syncthreads();
    gemm_mma(acc, smu, m0, n0, lane);
    __syncthreads();

    stage_w(smu, layer, OFF_NW1 + 128 * 128, tid);
    #pragma unroll
    for (int i = 0; i < 8; i++) {
        int lin = tid + i * 256;
        int r = lin >> 5, q = (lin & 31) * 4;
        int n = b0n + r;
        bool valid = (n < NNODES);
        if (!valid) n = NNODES - 1;
        float4* sp = (float4*)(g_sum + (size_t)n * HID + q);
        float4 v = *sp;
        if (valid) *sp = make_float4(0.f, 0.f, 0.f, 0.f);
        float s = s_scale[r];
        v.x *= s; v.y *= s; v.z *= s; v.w *= s;
        stage_a4(smh, r, q, v);
    }
    CP_WAIT0();
    __syncthreads();
    gemm_mma(acc, smu, m0, n0, lane);
    __syncthreads();

    stage_w(smu, layer, OFF_NW2, tid);
    #pragma unroll
    for (int mt = 0; mt < 2; mt++)
        #pragma unroll
        for (int h = 0; h < 2; h++) {
            int r = m0 + mt * 16 + h * 8 + g;
            #pragma unroll
            for (int nt = 0; nt < 4; nt++) {
                int c0 = n0 + nt * 8 + 2 * t;
                float v0 = fmaxf(acc[mt][nt][2 * h]     + s_b1[c0],     0.f);
                float v1 = fmaxf(acc[mt][nt][2 * h + 1] + s_b1[c0 + 1], 0.f);
                ushort2 hh, ll;
                bsplit(v0, hh.x, ll.x); bsplit(v1, hh.y, ll.y);
                *(ushort2*)(smh + A_HIo + r * SAH + c0) = hh;
                *(ushort2*)(smh + A_LOo + r * SAH + c0) = ll;
            }
        }
    CP_WAIT0();
    __syncthreads();

    ACC_ZERO(acc);
    gemm_mma(acc, smu, m0, n0, lane);

    #pragma unroll
    for (int mt = 0; mt < 2; mt++)
        #pragma unroll
        for (int h = 0; h < 2; h++) {
            int r = m0 + mt * 16 + h * 8 + g;
            int gn = b0n + r;
            if (gn >= NNODES) continue;
            #pragma unroll
            for (int nt = 0; nt < 4; nt++) {
                int c0 = n0 + nt * 8 + 2 * t;
                float2* xp = (float2*)(g_x + (size_t)gn * HID + c0);
                float2 xo = *xp;
                xo.x += acc[mt][nt][2 * h]     + s_b2[c0];
                xo.y += acc[mt][nt][2 * h + 1] + s_b2[c0 + 1];
                *xp = xo;
            }
        }
}

// ---------------- decoder + row-normalize -----------------------------------
__global__ void decode_kernel(const float* __restrict__ dw,
                              const float* __restrict__ db,
                              float* __restrict__ out) {
    int w = (blockIdx.x * blockDim.x + threadIdx.x) >> 5;
    int lane = threadIdx.x & 31;
    if (w >= NNODES) return;
    const float* xr = g_x + (size_t)w * HID;
    float a0 = 0.f, a1 = 0.f, a2 = 0.f;
    #pragma unroll
    for (int i = 0; i < 4; i++) {
        int k = lane + i * 32;
        float xv = xr[k];
        a0 += xv * __ldg(dw + k * 3 + 0);
        a1 += xv * __ldg(dw + k * 3 + 1);
        a2 += xv * __ldg(dw + k * 3 + 2);
    }
    #pragma unroll
    for (int o = 16; o; o >>= 1) {
        a0 += __shfl_xor_sync(0xffffffffu, a0, o);
        a1 += __shfl_xor_sync(0xffffffffu, a1, o);
        a2 += __shfl_xor_sync(0xffffffffu, a2, o);
    }
    if (lane == 0) {
        a0 += __ldg(db + 0); a1 += __ldg(db + 1); a2 += __ldg(db + 2);
        float nrm = sqrtf(a0 * a0 + a1 * a1 + a2 * a2);
        float inv = 1.0f / fmaxf(nrm, 1e-12f);
        out[(size_t)w * 3 + 0] = a0 * inv;
        out[(size_t)w * 3 + 1] = a1 * inv;
        out[(size_t)w * 3 + 2] = a2 * inv;
    }
}

// ---------------- launcher ----------------------------------------------------
extern "C" void kernel_launch(void* const* d_in, const int* in_sizes, int n_in,
                              void* d_out, int out_size) {
    (void)in_sizes; (void)n_in; (void)out_size;
    const float* edge_attr = (const float*)d_in[1];
    const void*  ei        = d_in[2];
    const float* enc_w = (const float*)d_in[3];
    const float* enc_b = (const float*)d_in[4];
    const float* dec_w = (const float*)d_in[5];
    const float* dec_b = (const float*)d_in[6];
    const float* ew1   = (const float*)d_in[7];
    const float* eb1   = (const float*)d_in[8];
    const float* ew2   = (const float*)d_in[9];
    const float* eb2   = (const float*)d_in[10];
    const float* nw1   = (const float*)d_in[11];
    const float* nb1   = (const float*)d_in[12];
    const float* nw2   = (const float*)d_in[13];
    const float* nb2   = (const float*)d_in[14];

    cudaFuncSetAttribute(proj_kernel, cudaFuncAttributeMaxDynamicSharedMemorySize, SMEM_DYN);
    cudaFuncSetAttribute(edge_kernel, cudaFuncAttributeMaxDynamicSharedMemorySize, SMEM_DYN_E);
    cudaFuncSetAttribute(node_kernel, cudaFuncAttributeMaxDynamicSharedMemorySize, SMEM_DYN);
    cudaGetLastError();

    {
        size_t n4 = (size_t)NNODES * HID / 4;
        zero_detect_kernel<<<(unsigned)((n4 + 255) / 256), 256>>>(
            (const unsigned int*)ei);
    }
    {
        int blocks = CONV_BLOCKS + (NWSPLIT + 255) / 256;
        convert_wsplit_kernel<<<blocks, 256>>>(ei, ew1, ew2, nw1, nw2);
    }
    encode_degree_kernel<<<NEDGES * 32 / 256, 256>>>(edge_attr, enc_w, enc_b);

    // #4 edge layer 0 (Pa=Pb=0 from zeroing) -- profiled launch
    edge_kernel<<<NEDGES / 64, 256, SMEM_DYN_E>>>(0, eb1, eb2);

    cntinv_kernel<<<(NNODES + 255) / 256, 256>>>();
    node_kernel<<<(NNODES + 63) / 64, 256, SMEM_DYN>>>(0, nb1, nb2);

    for (int l = 1; l < NLAYERS; l++) {
        proj_kernel<<<(NNODES + 63) / 64, 256, SMEM_DYN>>>(l);
        edge_kernel<<<NEDGES / 64, 256, SMEM_DYN_E>>>(
            l, eb1 + (size_t)l * HID, eb2 + (size_t)l * HID);
        node_kernel<<<(NNODES + 63) / 64, 256, SMEM_DYN>>>(
            l, nb1 + (size_t)l * HID, nb2 + (size_t)l * HID);
    }

    decode_kernel<<<(NNODES * 32 + 255) / 256, 256>>>(dec_w, dec_b, (float*)d_out);
}